// round 13
// baseline (speedup 1.0000x reference)
#include <cuda_runtime.h>
#include <cuda_bf16.h>

// ---------------------------------------------------------------------------
// RPN training loss (faithful port of the buggy reference), SINGLE KERNEL:
//   gt_idx[i] = argmax_j IoU(anchor_i, gt_j)   (first-max wins ties)
//   label = 1 if gt_idx >= 1, 0 if gt_idx == 0  (every anchor is pos or neg)
//   sel   = first min(num_pos,128) positives by anchor index, then negatives
//           by anchor index (spilling back into positives if negatives run out)
//   cls   = mean softmax-CE over 256 samples
//   reg   = mean over 256 of 2 * sum smoothL1(label * (pred - encode))
//
// Grid = 33 blocks x 512 threads: block 0 = dedicated TAIL (spin-polls warp
// words, ONE per thread); blocks 1..32 = FRONT covering anchors [0, 2048),
// EIGHT threads per anchor, merged with 3 shfl_xor steps (division-free
// rational compare + exact min-index tie-break => global first-max, matching
// jnp.argmax).
//
// Each front warp owns 4 anchors and publishes ONE u64 containing the pos
// nibble, neg nibble, and the four 12-bit gt indices. Any word covering a
// valid anchor is provably nonzero (every valid anchor is pos or neg), so
// the tail polls for nonzero — no atomics, no fences, no separate gt_idx
// traffic. (For M > 4095, an exact fenced g_gt_idx path is used.)
// Tail: poll 512 words (1/thread) -> smem; warp 0 assembles 32-anchor masks
// AND scans the 64 group popcounts in one pass -> offsets/totals; smem-only
// scatter of first-128 pos/neg; 256-sample loss (fast MUFU intrinsics --
// 1e-3 rel-err budget vs ~1e-6 intrinsic error) reading gt indices straight
// from the polled words; shfl reduction. Tail re-zeroes words (replay-safe).
// Exact whole-N fallback if the 2048-anchor front lacks 128 pos or 128 neg.
// ---------------------------------------------------------------------------

#define NMAX     (1 << 20)
#define THR      512
#define NFB      32                  // front blocks
#define GRID_T   (NFB + 1)
#define APB      64                  // anchors per front block (16 warps x 4)
#define FRONT    (NFB * APB)         // 2048
#define NGRP     (FRONT / 32)        // 64 groups of 32 anchors
#define NWRD     (FRONT / 4)         // 512 u64 warp words (4 anchors each)
#define CAP      256

__device__ int g_gt_idx[NMAX];                       // fallback / huge-M only
__device__ __align__(8) unsigned long long g_wrd[NWRD];  // zero-init; tail resets

__device__ __forceinline__ int wrd_idx(unsigned long long w, int slot) {
    return (int)((w >> (8 + 12 * slot)) & 0xFFFull);
}

// ---- full-M division-free argmax from global (fallback path) -------------
__device__ __forceinline__ int argmax_iou_global(const float4 a,
                                                 const float4* __restrict__ gt,
                                                 int M) {
    float areaA = (a.z - a.x) * (a.w - a.y);
    float bI = 0.0f, bU = 1.0f;
    int best = 0;
    #pragma unroll 4
    for (int j = 0; j < M; ++j) {
        float4 g = __ldg(&gt[j]);
        float areaB = (g.z - g.x) * (g.w - g.y);
        float w = fmaxf(fminf(a.z, g.z) - fmaxf(a.x, g.x), 0.0f);
        float h = fmaxf(fminf(a.w, g.w) - fmaxf(a.y, g.y), 0.0f);
        float inter = w * h;
        float uni = (areaA + areaB) - inter;
        bool u = inter * bU > bI * uni;
        bI = u ? inter : bI;  bU = u ? uni : bU;  best = u ? j : best;
    }
    return best;
}

__global__ void __launch_bounds__(THR, 1)
k_fused(const float2* __restrict__ score,
        const float4* __restrict__ pred,
        const float4* __restrict__ anchors,
        const float4* __restrict__ gt,
        float* __restrict__ out,
        int N, int M) {
    int t = threadIdx.x;
    int lane = t & 31;
    int warp = t >> 5;
    unsigned ltmask = (1u << lane) - 1u;

    if (blockIdx.x != 0) {
        // =================== FRONT block (1..NFB) ===================
        int f = blockIdx.x - 1;
        int base = f * APB;

        // prefetch this block's score/pred lines into L2 for the tail's gathers
        {
            const char* sb = (const char*)(score + base);   // 512 B
            const char* pb = (const char*)(pred + base);    // 1024 B
            if (t < 4) {
                asm volatile("prefetch.global.L2 [%0];" :: "l"(sb + t * 128));
            } else if (t < 12) {
                asm volatile("prefetch.global.L2 [%0];" :: "l"(pb + (t - 4) * 128));
            }
        }

        // 8 threads per anchor: lane = sub*4 + a_local
        int sub = lane >> 2;
        int al  = lane & 3;
        int i = base + warp * 4 + al;
        bool valid = (i < N);
        int bb;
        {
            float4 a = valid ? __ldg(&anchors[i])
                             : make_float4(0.f, 0.f, 1.f, 1.f);
            float areaA = (a.z - a.x) * (a.w - a.y);
            float bI = 0.0f, bU = 1.0f;
            bb = sub;        // chain's first index; zero-IoU chains only win
                             // merges via min-index tie-break -> global 0 ok
            #pragma unroll 4
            for (int j = sub; j < M; j += 8) {
                float4 g = __ldg(&gt[j]);
                float areaB = (g.z - g.x) * (g.w - g.y);
                float w = fmaxf(fminf(a.z, g.z) - fmaxf(a.x, g.x), 0.0f);
                float h = fmaxf(fminf(a.w, g.w) - fmaxf(a.y, g.y), 0.0f);
                float inter = w * h;
                float uni = (areaA + areaB) - inter;
                bool u = inter * bU > bI * uni;   // strict > : first max kept
                bI = u ? inter : bI;  bU = u ? uni : bU;  bb = u ? j : bb;
            }
            // merge the 8 chains (xor 4, 8, 16); exact tie-break -> min index
            #pragma unroll
            for (int o = 4; o <= 16; o <<= 1) {
                float oI = __shfl_xor_sync(0xffffffffu, bI, o);
                float oU = __shfl_xor_sync(0xffffffffu, bU, o);
                int   ob = __shfl_xor_sync(0xffffffffu, bb, o);
                float l = oI * bU, r = bI * oU;
                bool take = (l > r) || (l == r && ob < bb);
                bI = take ? oI : bI;  bU = take ? oU : bU;  bb = take ? ob : bb;
            }
        }
        if (M > 4095) {
            // huge-M: indices don't fit the word; use fenced g_gt_idx path
            if (valid && sub == 0) g_gt_idx[i] = bb;
            __threadfence();
        }
        unsigned bp = __ballot_sync(0xffffffffu, sub == 0 && valid && bb >= 1) & 0xFu;
        unsigned bn = __ballot_sync(0xffffffffu, sub == 0 && valid && bb == 0) & 0xFu;
        int b0 = __shfl_sync(0xffffffffu, bb, 0);
        int b1 = __shfl_sync(0xffffffffu, bb, 1);
        int b2 = __shfl_sync(0xffffffffu, bb, 2);
        int b3 = __shfl_sync(0xffffffffu, bb, 3);
        if (lane == 0) {
            unsigned long long w64 =
                (unsigned long long)bp | ((unsigned long long)bn << 4);
            if (M <= 4095) {
                w64 |= ((unsigned long long)(b0 & 0xFFF)) << 8;
                w64 |= ((unsigned long long)(b1 & 0xFFF)) << 20;
                w64 |= ((unsigned long long)(b2 & 0xFFF)) << 32;
                w64 |= ((unsigned long long)(b3 & 0xFFF)) << 44;
            }
            g_wrd[f * 16 + warp] = w64;
        }
        return;
    }

    // =================== TAIL block (blockIdx 0) ===================
    __shared__ unsigned long long s_w[NWRD];
    __shared__ unsigned s_pm[NGRP], s_nm[NGRP];
    __shared__ int s_po[NGRP], s_no[NGRP];
    __shared__ int s_pos[CAP], s_neg[CAP];
    __shared__ int s_maxg, s_nump, s_numn;
    __shared__ int s_cntp, s_cntn;
    __shared__ int wps[16], wns[16];
    __shared__ float s_rc[16], s_rr[16];

    // independent inits first (overlap with poll below)
    if (t < CAP) { s_pos[t] = 0; s_neg[t] = 0; }
    if (t == 0) { s_cntp = 0; s_cntn = 0; }

    // ---- poll phase: ONE u64 word per thread (NWRD == THR) ----
    {
        volatile unsigned long long* vm =
            reinterpret_cast<volatile unsigned long long*>(g_wrd);
        unsigned long long v = 0ull;
        if (4 * t < N) { do { v = vm[t]; } while (v == 0ull); }
        s_w[t] = v;
        g_wrd[t] = 0ull;                   // reset for next (graph) replay
    }
    __syncthreads();
    if (M > 4095) __threadfence();         // acquire for g_gt_idx path

    // ---- warp 0: assemble 32-anchor masks AND scan, one pass ----
    if (warp == 0) {
        unsigned pmk[2], nmk[2];
        int cp[2], cn[2];
        int sump = 0, sumn = 0;
        #pragma unroll
        for (int k = 0; k < 2; ++k) {
            int g = lane * 2 + k;
            unsigned pm = 0, nm = 0;
            #pragma unroll
            for (int q = 0; q < 8; ++q) {
                unsigned long long w = s_w[g * 8 + q];
                pm |= ((unsigned)(w        & 0xFull)) << (4 * q);
                nm |= ((unsigned)((w >> 4) & 0xFull)) << (4 * q);
            }
            pmk[k] = pm;  nmk[k] = nm;
            s_pm[g] = pm;
            s_nm[g] = nm;
            cp[k] = __popc(pm);
            cn[k] = __popc(nm);
            sump += cp[k];
            sumn += cn[k];
        }
        int ip = sump, in_ = sumn;
        #pragma unroll
        for (int o = 1; o < 32; o <<= 1) {
            int vp = __shfl_up_sync(0xffffffffu, ip, o);
            int vn = __shfl_up_sync(0xffffffffu, in_, o);
            if (lane >= o) { ip += vp; in_ += vn; }
        }
        int rp = ip - sump;
        int rn = in_ - sumn;
        int need = -1;
        #pragma unroll
        for (int k = 0; k < 2; ++k) {
            int g = lane * 2 + k;
            s_po[g] = rp;
            s_no[g] = rn;
            if (rp < 128 || rn < 128) need = g;
            rp += cp[k];
            rn += cn[k];
        }
        int mg = need + 1;
        #pragma unroll
        for (int o = 16; o > 0; o >>= 1)
            mg = max(mg, __shfl_xor_sync(0xffffffffu, mg, o));
        if (lane == 31) {
            s_maxg = max(mg, 1);
            s_nump = ip;
            s_numn = in_;
        }
    }
    __syncthreads();

    int num_pos = s_nump;
    int num_neg = s_numn;
    bool suff = (num_pos >= 128) && (num_neg >= 128);
    bool use_words = suff && (M <= 4095);

    if (suff) {
        // ---- smem-only scatter of first-128 pos/neg anchors ----
        int maxg = s_maxg;
        for (int g = warp; g < maxg; g += 16) {
            int po = s_po[g], no = s_no[g];
            if (po >= 128 && no >= 128) continue;
            unsigned pm = s_pm[g], nm = s_nm[g];
            int idx = g * 32 + lane;
            if ((pm >> lane) & 1u) {
                int r = po + __popc(pm & ltmask);
                if (r < 128) s_pos[r] = idx;
            }
            if ((nm >> lane) & 1u) {
                int r = no + __popc(nm & ltmask);
                if (r < 128) s_neg[r] = idx;
            }
        }
        __syncthreads();
    } else {
        // ---- exact fallback: materialize g_gt_idx for all anchors, then
        //      ordered chunk scan of the whole array (totals + lists exact) ----
        if (M <= 4095) {
            int fl = min(FRONT, N);
            for (int ii = t; ii < fl; ii += THR)
                g_gt_idx[ii] = wrd_idx(s_w[ii >> 2], ii & 3);
        }
        for (int ii = FRONT + t; ii < N; ii += THR) {
            g_gt_idx[ii] = argmax_iou_global(__ldg(&anchors[ii]), gt, M);
        }
        __syncthreads();
        int gi0 = (t < N) ? g_gt_idx[t] : -1;
        for (int base = 0; base < N; base += THR) {
            int idx1 = base + THR + t;
            int gi1 = (idx1 < N) ? g_gt_idx[idx1] : -1;
            int cp0 = s_cntp, cn0 = s_cntn;
            int is_pos = (gi0 >= 1);
            int is_neg = (gi0 == 0);
            unsigned mp = __ballot_sync(0xffffffffu, is_pos);
            unsigned mn = __ballot_sync(0xffffffffu, is_neg);
            if (lane == 0) { wps[warp] = __popc(mp); wns[warp] = __popc(mn); }
            __syncthreads();
            int basep = 0, basen = 0;
            for (int w = 0; w < warp; ++w) { basep += wps[w]; basen += wns[w]; }
            if (is_pos) {
                int r = cp0 + basep + __popc(mp & ltmask);
                if (r < CAP) s_pos[r] = base + t;
            }
            if (is_neg) {
                int r = cn0 + basen + __popc(mn & ltmask);
                if (r < CAP) s_neg[r] = base + t;
            }
            if (t == 0) {
                int tp = 0, tn = 0;
                #pragma unroll
                for (int w = 0; w < 16; ++w) { tp += wps[w]; tn += wns[w]; }
                s_cntp = cp0 + tp;
                s_cntn = cn0 + tn;
            }
            __syncthreads();
            if (s_cntp >= CAP && s_cntn >= CAP) break;
            gi0 = gi1;
        }
        num_pos = s_cntp;
        num_neg = s_cntn;
    }

    // ---- 256-sample loss: threads 0..255 take one sample each ----
    float csum = 0.0f, rsum = 0.0f;
    if (t < 256) {
        int cur_pos = min(num_pos, 128);
        int a, label;
        if (t < cur_pos) {
            a = s_pos[t];
            label = 1;
        } else {
            int j = t - cur_pos;
            if (j < num_neg) {
                a = s_neg[min(j, CAP - 1)];
                label = 0;
            } else {
                // stable neg_order spills into positives in anchor-index order
                a = s_pos[min(j - num_neg, CAP - 1)];
                label = 1;
            }
        }

        // classification: -log_softmax(score[a])[label] (fast intrinsics;
        // rel-err budget 1e-3 >> ~1e-6 intrinsic error)
        float2 s = __ldg(&score[a]);
        float m = fmaxf(s.x, s.y);
        float lse = m + __logf(__expf(s.x - m) + __expf(s.y - m));
        csum = lse - (label ? s.y : s.x);

        // regression: smooth-L1 on encoded target, zeroed for negatives
        float4 ab = __ldg(&anchors[a]);
        int gi = use_words ? wrd_idx(s_w[a >> 2], a & 3) : g_gt_idx[a];
        float4 gb = __ldg(&gt[gi]);
        float aw = ab.z - ab.x, ah = ab.w - ab.y;
        float acx = ab.x + 0.5f * aw, acy = ab.y + 0.5f * ah;
        float gw = gb.z - gb.x, gh = gb.w - gb.y;
        float gcx = gb.x + 0.5f * gw, gcy = gb.y + 0.5f * gh;
        float t0 = __fdividef(gcx - acx, aw);
        float t1 = __fdividef(gcy - acy, ah);
        float t2 = __logf(__fdividef(gw, aw));
        float t3 = __logf(__fdividef(gh, ah));
        float4 p = __ldg(&pred[a]);
        float fl = (float)label;
        float d0 = fl * (p.x - t0);
        float d1 = fl * (p.y - t1);
        float d2 = fl * (p.z - t2);
        float d3 = fl * (p.w - t3);
        float ad0 = fabsf(d0), ad1 = fabsf(d1), ad2 = fabsf(d2), ad3 = fabsf(d3);
        float s0 = (ad0 < 1.0f) ? 0.5f * d0 * d0 : ad0 - 0.5f;
        float s1 = (ad1 < 1.0f) ? 0.5f * d1 * d1 : ad1 - 0.5f;
        float s2 = (ad2 < 1.0f) ? 0.5f * d2 * d2 : ad2 - 0.5f;
        float s3 = (ad3 < 1.0f) ? 0.5f * d3 * d3 : ad3 - 0.5f;
        rsum = 2.0f * (s0 + s1 + s2 + s3);
    }

    // ---- reduction: shfl within warps + 16 partials ----
    #pragma unroll
    for (int o = 16; o > 0; o >>= 1) {
        csum += __shfl_down_sync(0xffffffffu, csum, o);
        rsum += __shfl_down_sync(0xffffffffu, rsum, o);
    }
    if (lane == 0) { s_rc[warp] = csum; s_rr[warp] = rsum; }
    __syncthreads();
    if (t == 0) {
        float c = 0.0f, r = 0.0f;
        #pragma unroll
        for (int w = 0; w < 16; ++w) { c += s_rc[w]; r += s_rr[w]; }
        out[0] = c * (1.0f / 256.0f);   // CLS_W = 1.0
        out[1] = r * (1.0f / 256.0f);
    }
}

extern "C" void kernel_launch(void* const* d_in, const int* in_sizes, int n_in,
                              void* d_out, int out_size) {
    const float2* score   = (const float2*)d_in[0];   // [N,2]
    const float4* pred    = (const float4*)d_in[1];   // [N,4]
    const float4* anchors = (const float4*)d_in[2];   // [N,4]
    const float4* gt      = (const float4*)d_in[3];   // [M,4]
    float* out = (float*)d_out;

    int N = in_sizes[2] / 4;
    int M = in_sizes[3] / 4;

    k_fused<<<GRID_T, THR>>>(score, pred, anchors, gt, out, N, M);
}

// round 14
// speedup vs baseline: 1.0295x; 1.0295x over previous
#include <cuda_runtime.h>
#include <cuda_bf16.h>

// ---------------------------------------------------------------------------
// RPN training loss (faithful port of the buggy reference), SINGLE KERNEL:
//   gt_idx[i] = argmax_j IoU(anchor_i, gt_j)   (first-max wins ties)
//   label = 1 if gt_idx >= 1, 0 if gt_idx == 0  (every anchor is pos or neg)
//   sel   = first min(num_pos,128) positives by anchor index, then negatives
//           by anchor index (spilling back into positives if negatives run out)
//   cls   = mean softmax-CE over 256 samples
//   reg   = mean over 256 of 2 * sum smoothL1(label * (pred - encode))
//
// Grid = 25 blocks x 512 threads: block 0 = dedicated TAIL (spin-polls warp
// words, ONE per thread); blocks 1..24 = FRONT covering anchors [0, 1536),
// EIGHT threads per anchor, merged with 3 shfl_xor steps (division-free
// rational compare + exact min-index tie-break => global first-max, matching
// jnp.argmax).
//
// When the window holds >=128 pos AND >=128 neg, the selection mapping uses
// the totals only through min(.,128) and j<num_neg with j<128 — i.e. only
// ">=128" matters — so the 1536-anchor window is semantically identical to
// scanning all N on the fast path. Exact whole-N fallback otherwise.
//
// Each front warp owns 4 anchors and publishes ONE u64 containing the pos
// nibble, neg nibble, and the four 12-bit gt indices. Any word covering a
// valid anchor is provably nonzero (every valid anchor is pos or neg), so
// the tail polls for nonzero — no atomics, no fences, no separate gt_idx
// traffic. (For M > 4095, an exact fenced g_gt_idx path is used.)
// Tail: poll 384 words (1/thread) -> smem; warp 0 assembles 32-anchor masks
// AND scans the group popcounts in one pass -> offsets/totals; smem-only
// scatter of first-128 pos/neg; 256-sample loss (fast MUFU intrinsics —
// 1e-3 rel-err budget vs ~1e-6 intrinsic error) reading gt indices straight
// from the polled words; shfl reduction. Tail re-zeroes words (replay-safe).
// ---------------------------------------------------------------------------

#define NMAX     (1 << 20)
#define THR      512
#define NFB      24                  // front blocks
#define GRID_T   (NFB + 1)
#define APB      64                  // anchors per front block (16 warps x 4)
#define FRONT    (NFB * APB)         // 1536
#define NGRP     48                  // groups of 32 anchors in window
#define NGRP_PAD 64                  // padded for the one-warp scan
#define NWRD     (FRONT / 4)         // 384 u64 warp words (4 anchors each)
#define CAP      256

__device__ int g_gt_idx[NMAX];                       // fallback / huge-M only
__device__ __align__(8) unsigned long long g_wrd[NWRD];  // zero-init; tail resets

__device__ __forceinline__ int wrd_idx(unsigned long long w, int slot) {
    return (int)((w >> (8 + 12 * slot)) & 0xFFFull);
}

// ---- full-M division-free argmax from global (fallback path) -------------
__device__ __forceinline__ int argmax_iou_global(const float4 a,
                                                 const float4* __restrict__ gt,
                                                 int M) {
    float areaA = (a.z - a.x) * (a.w - a.y);
    float bI = 0.0f, bU = 1.0f;
    int best = 0;
    #pragma unroll 4
    for (int j = 0; j < M; ++j) {
        float4 g = __ldg(&gt[j]);
        float areaB = (g.z - g.x) * (g.w - g.y);
        float w = fmaxf(fminf(a.z, g.z) - fmaxf(a.x, g.x), 0.0f);
        float h = fmaxf(fminf(a.w, g.w) - fmaxf(a.y, g.y), 0.0f);
        float inter = w * h;
        float uni = (areaA + areaB) - inter;
        bool u = inter * bU > bI * uni;
        bI = u ? inter : bI;  bU = u ? uni : bU;  best = u ? j : best;
    }
    return best;
}

__global__ void __launch_bounds__(THR, 1)
k_fused(const float2* __restrict__ score,
        const float4* __restrict__ pred,
        const float4* __restrict__ anchors,
        const float4* __restrict__ gt,
        float* __restrict__ out,
        int N, int M) {
    int t = threadIdx.x;
    int lane = t & 31;
    int warp = t >> 5;
    unsigned ltmask = (1u << lane) - 1u;

    if (blockIdx.x != 0) {
        // =================== FRONT block (1..NFB) ===================
        int f = blockIdx.x - 1;
        int base = f * APB;

        // prefetch this block's score/pred lines into L2 for the tail's gathers
        {
            const char* sb = (const char*)(score + base);   // 512 B
            const char* pb = (const char*)(pred + base);    // 1024 B
            if (t < 4) {
                asm volatile("prefetch.global.L2 [%0];" :: "l"(sb + t * 128));
            } else if (t < 12) {
                asm volatile("prefetch.global.L2 [%0];" :: "l"(pb + (t - 4) * 128));
            }
        }

        // 8 threads per anchor: lane = sub*4 + a_local
        int sub = lane >> 2;
        int al  = lane & 3;
        int i = base + warp * 4 + al;
        bool valid = (i < N);
        int bb;
        {
            float4 a = valid ? __ldg(&anchors[i])
                             : make_float4(0.f, 0.f, 1.f, 1.f);
            float areaA = (a.z - a.x) * (a.w - a.y);
            float bI = 0.0f, bU = 1.0f;
            bb = sub;        // chain's first index; zero-IoU chains only win
                             // merges via min-index tie-break -> global 0 ok
            #pragma unroll 4
            for (int j = sub; j < M; j += 8) {
                float4 g = __ldg(&gt[j]);
                float areaB = (g.z - g.x) * (g.w - g.y);
                float w = fmaxf(fminf(a.z, g.z) - fmaxf(a.x, g.x), 0.0f);
                float h = fmaxf(fminf(a.w, g.w) - fmaxf(a.y, g.y), 0.0f);
                float inter = w * h;
                float uni = (areaA + areaB) - inter;
                bool u = inter * bU > bI * uni;   // strict > : first max kept
                bI = u ? inter : bI;  bU = u ? uni : bU;  bb = u ? j : bb;
            }
            // merge the 8 chains (xor 4, 8, 16); exact tie-break -> min index
            #pragma unroll
            for (int o = 4; o <= 16; o <<= 1) {
                float oI = __shfl_xor_sync(0xffffffffu, bI, o);
                float oU = __shfl_xor_sync(0xffffffffu, bU, o);
                int   ob = __shfl_xor_sync(0xffffffffu, bb, o);
                float l = oI * bU, r = bI * oU;
                bool take = (l > r) || (l == r && ob < bb);
                bI = take ? oI : bI;  bU = take ? oU : bU;  bb = take ? ob : bb;
            }
        }
        if (M > 4095) {
            // huge-M: indices don't fit the word; use fenced g_gt_idx path
            if (valid && sub == 0) g_gt_idx[i] = bb;
            __threadfence();
        }
        unsigned bp = __ballot_sync(0xffffffffu, sub == 0 && valid && bb >= 1) & 0xFu;
        unsigned bn = __ballot_sync(0xffffffffu, sub == 0 && valid && bb == 0) & 0xFu;
        int b0 = __shfl_sync(0xffffffffu, bb, 0);
        int b1 = __shfl_sync(0xffffffffu, bb, 1);
        int b2 = __shfl_sync(0xffffffffu, bb, 2);
        int b3 = __shfl_sync(0xffffffffu, bb, 3);
        if (lane == 0) {
            unsigned long long w64 =
                (unsigned long long)bp | ((unsigned long long)bn << 4);
            if (M <= 4095) {
                w64 |= ((unsigned long long)(b0 & 0xFFF)) << 8;
                w64 |= ((unsigned long long)(b1 & 0xFFF)) << 20;
                w64 |= ((unsigned long long)(b2 & 0xFFF)) << 32;
                w64 |= ((unsigned long long)(b3 & 0xFFF)) << 44;
            }
            g_wrd[f * 16 + warp] = w64;
        }
        return;
    }

    // =================== TAIL block (blockIdx 0) ===================
    __shared__ unsigned long long s_w[NWRD];
    __shared__ unsigned s_pm[NGRP_PAD], s_nm[NGRP_PAD];
    __shared__ int s_po[NGRP_PAD], s_no[NGRP_PAD];
    __shared__ int s_pos[CAP], s_neg[CAP];
    __shared__ int s_maxg, s_nump, s_numn;
    __shared__ int s_cntp, s_cntn;
    __shared__ int wps[16], wns[16];
    __shared__ float s_rc[16], s_rr[16];

    // independent inits first (overlap with poll below)
    if (t < CAP) { s_pos[t] = 0; s_neg[t] = 0; }
    if (t == 0) { s_cntp = 0; s_cntn = 0; }

    // ---- poll phase: ONE u64 word per thread (threads >= NWRD idle) ----
    if (t < NWRD) {
        volatile unsigned long long* vm =
            reinterpret_cast<volatile unsigned long long*>(g_wrd);
        unsigned long long v = 0ull;
        if (4 * t < N) { do { v = vm[t]; } while (v == 0ull); }
        s_w[t] = v;
        g_wrd[t] = 0ull;                   // reset for next (graph) replay
    }
    __syncthreads();
    if (M > 4095) __threadfence();         // acquire for g_gt_idx path

    // ---- warp 0: assemble 32-anchor masks AND scan, one pass ----
    if (warp == 0) {
        int cp[2], cn[2];
        int sump = 0, sumn = 0;
        #pragma unroll
        for (int k = 0; k < 2; ++k) {
            int g = lane * 2 + k;
            unsigned pm = 0, nm = 0;
            if (g < NGRP) {
                #pragma unroll
                for (int q = 0; q < 8; ++q) {
                    unsigned long long w = s_w[g * 8 + q];
                    pm |= ((unsigned)(w        & 0xFull)) << (4 * q);
                    nm |= ((unsigned)((w >> 4) & 0xFull)) << (4 * q);
                }
            }
            s_pm[g] = pm;
            s_nm[g] = nm;
            cp[k] = __popc(pm);
            cn[k] = __popc(nm);
            sump += cp[k];
            sumn += cn[k];
        }
        int ip = sump, in_ = sumn;
        #pragma unroll
        for (int o = 1; o < 32; o <<= 1) {
            int vp = __shfl_up_sync(0xffffffffu, ip, o);
            int vn = __shfl_up_sync(0xffffffffu, in_, o);
            if (lane >= o) { ip += vp; in_ += vn; }
        }
        int rp = ip - sump;
        int rn = in_ - sumn;
        int need = -1;
        #pragma unroll
        for (int k = 0; k < 2; ++k) {
            int g = lane * 2 + k;
            s_po[g] = rp;
            s_no[g] = rn;
            if ((rp < 128 || rn < 128) && g < NGRP) need = g;
            rp += cp[k];
            rn += cn[k];
        }
        int mg = need + 1;
        #pragma unroll
        for (int o = 16; o > 0; o >>= 1)
            mg = max(mg, __shfl_xor_sync(0xffffffffu, mg, o));
        if (lane == 31) {
            s_maxg = max(mg, 1);
            s_nump = ip;
            s_numn = in_;
        }
    }
    __syncthreads();

    int num_pos = s_nump;
    int num_neg = s_numn;
    bool suff = (num_pos >= 128) && (num_neg >= 128);
    bool use_words = suff && (M <= 4095);

    if (suff) {
        // ---- smem-only scatter of first-128 pos/neg anchors ----
        int maxg = s_maxg;
        for (int g = warp; g < maxg; g += 16) {
            int po = s_po[g], no = s_no[g];
            if (po >= 128 && no >= 128) continue;
            unsigned pm = s_pm[g], nm = s_nm[g];
            int idx = g * 32 + lane;
            if ((pm >> lane) & 1u) {
                int r = po + __popc(pm & ltmask);
                if (r < 128) s_pos[r] = idx;
            }
            if ((nm >> lane) & 1u) {
                int r = no + __popc(nm & ltmask);
                if (r < 128) s_neg[r] = idx;
            }
        }
        __syncthreads();
    } else {
        // ---- exact fallback: materialize g_gt_idx for all anchors, then
        //      ordered chunk scan of the whole array (totals + lists exact) ----
        if (M <= 4095) {
            int fl = min(FRONT, N);
            for (int ii = t; ii < fl; ii += THR)
                g_gt_idx[ii] = wrd_idx(s_w[ii >> 2], ii & 3);
        }
        for (int ii = FRONT + t; ii < N; ii += THR) {
            g_gt_idx[ii] = argmax_iou_global(__ldg(&anchors[ii]), gt, M);
        }
        __syncthreads();
        int gi0 = (t < N) ? g_gt_idx[t] : -1;
        for (int base = 0; base < N; base += THR) {
            int idx1 = base + THR + t;
            int gi1 = (idx1 < N) ? g_gt_idx[idx1] : -1;
            int cp0 = s_cntp, cn0 = s_cntn;
            int is_pos = (gi0 >= 1);
            int is_neg = (gi0 == 0);
            unsigned mp = __ballot_sync(0xffffffffu, is_pos);
            unsigned mn = __ballot_sync(0xffffffffu, is_neg);
            if (lane == 0) { wps[warp] = __popc(mp); wns[warp] = __popc(mn); }
            __syncthreads();
            int basep = 0, basen = 0;
            for (int w = 0; w < warp; ++w) { basep += wps[w]; basen += wns[w]; }
            if (is_pos) {
                int r = cp0 + basep + __popc(mp & ltmask);
                if (r < CAP) s_pos[r] = base + t;
            }
            if (is_neg) {
                int r = cn0 + basen + __popc(mn & ltmask);
                if (r < CAP) s_neg[r] = base + t;
            }
            if (t == 0) {
                int tp = 0, tn = 0;
                #pragma unroll
                for (int w = 0; w < 16; ++w) { tp += wps[w]; tn += wns[w]; }
                s_cntp = cp0 + tp;
                s_cntn = cn0 + tn;
            }
            __syncthreads();
            if (s_cntp >= CAP && s_cntn >= CAP) break;
            gi0 = gi1;
        }
        num_pos = s_cntp;
        num_neg = s_cntn;
    }

    // ---- 256-sample loss: threads 0..255 take one sample each ----
    float csum = 0.0f, rsum = 0.0f;
    if (t < 256) {
        int cur_pos = min(num_pos, 128);
        int a, label;
        if (t < cur_pos) {
            a = s_pos[t];
            label = 1;
        } else {
            int j = t - cur_pos;
            if (j < num_neg) {
                a = s_neg[min(j, CAP - 1)];
                label = 0;
            } else {
                // stable neg_order spills into positives in anchor-index order
                a = s_pos[min(j - num_neg, CAP - 1)];
                label = 1;
            }
        }

        // classification: -log_softmax(score[a])[label] (fast intrinsics;
        // rel-err budget 1e-3 >> ~1e-6 intrinsic error)
        float2 s = __ldg(&score[a]);
        float m = fmaxf(s.x, s.y);
        float lse = m + __logf(__expf(s.x - m) + __expf(s.y - m));
        csum = lse - (label ? s.y : s.x);

        // regression: smooth-L1 on encoded target, zeroed for negatives
        float4 ab = __ldg(&anchors[a]);
        int gi = use_words ? wrd_idx(s_w[a >> 2], a & 3) : g_gt_idx[a];
        float4 gb = __ldg(&gt[gi]);
        float aw = ab.z - ab.x, ah = ab.w - ab.y;
        float acx = ab.x + 0.5f * aw, acy = ab.y + 0.5f * ah;
        float gw = gb.z - gb.x, gh = gb.w - gb.y;
        float gcx = gb.x + 0.5f * gw, gcy = gb.y + 0.5f * gh;
        float t0 = __fdividef(gcx - acx, aw);
        float t1 = __fdividef(gcy - acy, ah);
        float t2 = __logf(__fdividef(gw, aw));
        float t3 = __logf(__fdividef(gh, ah));
        float4 p = __ldg(&pred[a]);
        float fl = (float)label;
        float d0 = fl * (p.x - t0);
        float d1 = fl * (p.y - t1);
        float d2 = fl * (p.z - t2);
        float d3 = fl * (p.w - t3);
        float ad0 = fabsf(d0), ad1 = fabsf(d1), ad2 = fabsf(d2), ad3 = fabsf(d3);
        float s0 = (ad0 < 1.0f) ? 0.5f * d0 * d0 : ad0 - 0.5f;
        float s1 = (ad1 < 1.0f) ? 0.5f * d1 * d1 : ad1 - 0.5f;
        float s2 = (ad2 < 1.0f) ? 0.5f * d2 * d2 : ad2 - 0.5f;
        float s3 = (ad3 < 1.0f) ? 0.5f * d3 * d3 : ad3 - 0.5f;
        rsum = 2.0f * (s0 + s1 + s2 + s3);
    }

    // ---- reduction: shfl within warps + 16 partials ----
    #pragma unroll
    for (int o = 16; o > 0; o >>= 1) {
        csum += __shfl_down_sync(0xffffffffu, csum, o);
        rsum += __shfl_down_sync(0xffffffffu, rsum, o);
    }
    if (lane == 0) { s_rc[warp] = csum; s_rr[warp] = rsum; }
    __syncthreads();
    if (t == 0) {
        float c = 0.0f, r = 0.0f;
        #pragma unroll
        for (int w = 0; w < 16; ++w) { c += s_rc[w]; r += s_rr[w]; }
        out[0] = c * (1.0f / 256.0f);   // CLS_W = 1.0
        out[1] = r * (1.0f / 256.0f);
    }
}

extern "C" void kernel_launch(void* const* d_in, const int* in_sizes, int n_in,
                              void* d_out, int out_size) {
    const float2* score   = (const float2*)d_in[0];   // [N,2]
    const float4* pred    = (const float4*)d_in[1];   // [N,4]
    const float4* anchors = (const float4*)d_in[2];   // [N,4]
    const float4* gt      = (const float4*)d_in[3];   // [M,4]
    float* out = (float*)d_out;

    int N = in_sizes[2] / 4;
    int M = in_sizes[3] / 4;

    k_fused<<<GRID_T, THR>>>(score, pred, anchors, gt, out, N, M);
}